// round 17
// baseline (speedup 1.0000x reference)
#include <cuda_runtime.h>
#include <cuda_bf16.h>
#include <cstdint>

// ---------------- problem constants ----------------
#define B     16
#define CIN   256
#define COUT  256
#define HW    4096
#define STY   512
#define KTOT  2304          // 9 taps * 256 ci; k = tap*256 + ci
#define KSTG  16
#define NSTG  144           // 2304 / 16

// ---------------- scratch ----------------
// weights: [b][stage s=tap*16+cib][co][16]   (stage-blocked, warp-coalesced)
// acts:    [b][cib][pix][16]                 (pixel-major within ci block)
__device__ float g_s[B * CIN];
__device__ __align__(16) __nv_bfloat16 g_wbh[(size_t)B * NSTG * COUT * 16];
__device__ __align__(16) __nv_bfloat16 g_wbl[(size_t)B * NSTG * COUT * 16];
__device__ __align__(16) __nv_bfloat16 g_xh[(size_t)B * 16 * HW * 16];
__device__ __align__(16) __nv_bfloat16 g_xl[(size_t)B * 16 * HW * 16];
__device__ __align__(64) unsigned char g_zero64[64];                    // zero-init

#define XB  ((size_t)16 * HW * 16)          // act elems per batch
#define WB  ((size_t)NSTG * COUT * 16)      // wgt elems per batch

// ---------------- helpers ----------------
__device__ __forceinline__ uint32_t smem_u32(const void* p) {
    uint32_t a;
    asm("{ .reg .u64 t; cvta.to.shared.u64 t, %1; cvt.u32.u64 %0, t; }" : "=r"(a) : "l"(p));
    return a;
}
__device__ __forceinline__ void ldsm_x4(uint32_t* r, uint32_t addr) {
    asm volatile("ldmatrix.sync.aligned.m8n8.x4.shared.b16 {%0,%1,%2,%3}, [%4];"
                 : "=r"(r[0]), "=r"(r[1]), "=r"(r[2]), "=r"(r[3]) : "r"(addr));
}
__device__ __forceinline__ void mma16816(float* c, const uint32_t* a,
                                         uint32_t b0, uint32_t b1) {
    asm volatile("mma.sync.aligned.m16n8k16.row.col.f32.bf16.bf16.f32 "
                 "{%0,%1,%2,%3}, {%4,%5,%6,%7}, {%8,%9}, {%0,%1,%2,%3};"
                 : "+f"(c[0]), "+f"(c[1]), "+f"(c[2]), "+f"(c[3])
                 : "r"(a[0]), "r"(a[1]), "r"(a[2]), "r"(a[3]), "r"(b0), "r"(b1));
}

// ---------------- smem: 48B-padded rows (32B data + 16B pad) ----------------
#define ROWB    48
#define A_HI_O  0
#define A_LO_O  6144
#define B_HI_O  12288
#define B_LO_O  18432
#define BUFB    24576
#define SMEM_TOTAL (3 * BUFB)   // 73728 -> 2 CTAs/SM

// ---------------------------------------------------------------------------
__global__ void style_kernel(const float* __restrict__ w_style,
                             const float* __restrict__ aff_w,
                             const float* __restrict__ aff_b) {
    int warp = blockIdx.x * (blockDim.x >> 5) + (threadIdx.x >> 5);
    int lane = threadIdx.x & 31;
    if (warp >= B * CIN) return;
    int b  = warp / CIN;
    int ci = warp % CIN;
    const float4* ws = reinterpret_cast<const float4*>(w_style + (size_t)b * STY);
    const float4* aw = reinterpret_cast<const float4*>(aff_w  + (size_t)ci * STY);
    float sum = 0.f;
    #pragma unroll
    for (int j = lane; j < STY / 4; j += 32) {
        float4 a = ws[j], c = aw[j];
        sum += a.x * c.x + a.y * c.y + a.z * c.z + a.w * c.w;
    }
    #pragma unroll
    for (int o = 16; o; o >>= 1) sum += __shfl_xor_sync(0xffffffffu, sum, o);
    if (lane == 0) g_s[b * CIN + ci] = sum + aff_b[ci] + 1.0f;
}

// ---------------------------------------------------------------------------
// modulate + demodulate -> g_wb[b][s][co][16], s = tap*16 + (ci>>4)
// ---------------------------------------------------------------------------
__global__ void modulate_kernel(const float* __restrict__ Wf) {
    int co = blockIdx.x;
    int b  = blockIdx.y;
    int ci = threadIdx.x;

    float s = g_s[b * CIN + ci];
    const float* wp = Wf + ((size_t)co * CIN + ci) * 9;
    float m[9];
    float ss = 0.f;
    #pragma unroll
    for (int t = 0; t < 9; t++) { m[t] = wp[t] * s; ss += m[t] * m[t]; }

    __shared__ float red[256];
    red[ci] = ss;
    __syncthreads();
    #pragma unroll
    for (int st = 128; st > 0; st >>= 1) {
        if (ci < st) red[ci] += red[ci + st];
        __syncthreads();
    }
    float d = rsqrtf(red[0] + 1e-8f);

    #pragma unroll
    for (int t = 0; t < 9; t++) {
        float w = m[t] * d;
        __nv_bfloat16 hi = __float2bfloat16_rn(w);
        __nv_bfloat16 lo = __float2bfloat16_rn(w - __bfloat162float(hi));
        int stg = t * 16 + (ci >> 4);
        size_t o = ((size_t)b * NSTG + stg) * (COUT * 16) + co * 16 + (ci & 15);
        g_wbh[o] = hi;
        g_wbl[o] = lo;
    }
}

// ---------------------------------------------------------------------------
// split/transpose x [b][ci][pix] fp32 -> [b][cib][pix][16] bf16 hi/lo
// ---------------------------------------------------------------------------
__global__ void split_kernel(const float* __restrict__ x) {
    __shared__ float t[32][33];
    int b  = blockIdx.z;
    int cb = blockIdx.y * 32;
    int pb = blockIdx.x * 32;
    int tx = threadIdx.x, ty = threadIdx.y;

    const float* xp = x + ((size_t)b * CIN + cb) * HW + pb;
    #pragma unroll
    for (int i = ty; i < 32; i += 8)
        t[i][tx] = xp[(size_t)i * HW + tx];
    __syncthreads();
    #pragma unroll
    for (int i = ty; i < 32; i += 8) {
        float v = t[tx][i];                      // ci = cb+tx, pix = pb+i
        __nv_bfloat16 h = __float2bfloat16_rn(v);
        int cib = (cb + tx) >> 4;
        size_t o = ((size_t)b * 16 + cib) * (HW * 16)
                 + (size_t)(pb + i) * 16 + (tx & 15);
        g_xh[o] = h;
        g_xl[o] = __float2bfloat16_rn(v - __bfloat162float(h));
    }
}

// ---------------------------------------------------------------------------
// conv implicit GEMM. CTA 128px x 128co, 256 thr = 8 warps (4M x 2N of
// 32x64 warp tiles). K staged 16, 3-buffer LDG->reg->STS pipeline,
// ONE __syncthreads per stage, 2 CTAs/SM, B-fragment double-buffering
// so ldsm latency hides under MMAs.
// ---------------------------------------------------------------------------
__global__ void __launch_bounds__(256, 2)
conv_kernel(float* __restrict__ out) {
    extern __shared__ __align__(16) char smem[];
    const uint32_t sbase = smem_u32(smem);

    const int tid   = threadIdx.x;
    const int wid   = tid >> 5;
    const int lane  = tid & 31;
    const int strip = blockIdx.x;          // 0..31 (128-px strips)
    const int coT   = blockIdx.y;          // 0..1
    const int b     = blockIdx.z;
    const int coBase = coT * 128;

    const int wm = (wid & 3) * 32;         // warp M origin
    const int wn = (wid >> 2) * 64;        // warp N origin
    const int lr = lane & 15;
    const int kb = ((lane >> 4) & 1) * 16; // 16B column select

    // staging: each thread 1 A row (32B) + 1 B row (32B); prec by tid>>7
    const int prec = tid >> 7;             // 0=hi, 1=lo
    const int row  = tid & 127;            // pixel row / local co
    const int apy  = (strip * 128 + row) >> 6;
    const int apx  = (strip * 128 + row) & 63;

    const __nv_bfloat16* xsrc = (prec ? g_xl : g_xh) + (size_t)b * XB;
    const __nv_bfloat16* wsrc = (prec ? g_wbl : g_wbh) + (size_t)b * WB
                              + (size_t)(coBase + row) * 16;
    const uint32_t aoff = (prec ? A_LO_O : A_HI_O) + row * ROWB;
    const uint32_t boff = (prec ? B_LO_O : B_HI_O) + row * ROWB;

    float acc[2][8][4];
    #pragma unroll
    for (int i = 0; i < 2; i++)
        #pragma unroll
        for (int j = 0; j < 8; j++)
            #pragma unroll
            for (int q = 0; q < 4; q++) acc[i][j][q] = 0.f;

    uint4 va0, va1, vb0, vb1;
    auto ldg = [&](int s) {
        int tap = s >> 4, cib = s & 15;
        int y = apy + tap / 3 - 1;
        int xx = apx + tap % 3 - 1;
        bool ok = (unsigned)y < 64u && (unsigned)xx < 64u;
        const uint4* ap = ok
            ? (const uint4*)(xsrc + ((size_t)cib * HW + (y * 64 + xx)) * 16)
            : (const uint4*)g_zero64;
        va0 = ap[0]; va1 = ap[1];
        const uint4* bp = (const uint4*)(wsrc + (size_t)s * (COUT * 16));
        vb0 = bp[0]; vb1 = bp[1];
    };
    auto sts = [&](int buf) {
        char* d = smem + buf * BUFB;
        *(uint4*)(d + aoff)      = va0;
        *(uint4*)(d + aoff + 16) = va1;
        *(uint4*)(d + boff)      = vb0;
        *(uint4*)(d + boff + 16) = vb1;
    };

    // prologue
    ldg(0); sts(0);
    ldg(1);
    __syncthreads();

    for (int s = 0; s < NSTG; s++) {
        const uint32_t bb = sbase + (s % 3) * BUFB;

        // stores for stage s+1 land early, under the MMA stream
        if (s + 1 < NSTG) sts((s + 1) % 3);
        if (s + 2 < NSTG) ldg(s + 2);

        // fragment loads: B group 0 first, then A (hh-MMAs need ah+bh only)
        uint32_t ah[8], al[8], bh[2][4], bl[2][4];
        ldsm_x4(bh[0], bb + B_HI_O + (wn + lr) * ROWB + kb);
        #pragma unroll
        for (int mt = 0; mt < 2; mt++)
            ldsm_x4(ah + mt * 4, bb + A_HI_O + (wm + mt * 16 + lr) * ROWB + kb);
        ldsm_x4(bl[0], bb + B_LO_O + (wn + lr) * ROWB + kb);
        #pragma unroll
        for (int mt = 0; mt < 2; mt++)
            ldsm_x4(al + mt * 4, bb + A_LO_O + (wm + mt * 16 + lr) * ROWB + kb);

        #pragma unroll
        for (int g = 0; g < 4; g++) {
            const int cur = g & 1;
            if (g < 3) {   // prefetch next group's B frags before this group's MMAs
                ldsm_x4(bh[cur ^ 1], bb + B_HI_O + (wn + (g + 1) * 16 + lr) * ROWB + kb);
                ldsm_x4(bl[cur ^ 1], bb + B_LO_O + (wn + (g + 1) * 16 + lr) * ROWB + kb);
            }
            #pragma unroll
            for (int mt = 0; mt < 2; mt++)
                #pragma unroll
                for (int j = 0; j < 2; j++)
                    mma16816(acc[mt][g * 2 + j], ah + mt * 4, bh[cur][j], bh[cur][j + 2]);
            #pragma unroll
            for (int mt = 0; mt < 2; mt++)
                #pragma unroll
                for (int j = 0; j < 2; j++)
                    mma16816(acc[mt][g * 2 + j], ah + mt * 4, bl[cur][j], bl[cur][j + 2]);
            #pragma unroll
            for (int mt = 0; mt < 2; mt++)
                #pragma unroll
                for (int j = 0; j < 2; j++)
                    mma16816(acc[mt][g * 2 + j], al + mt * 4, bh[cur][j], bh[cur][j + 2]);
        }

        __syncthreads();
    }

    // ---- epilogue: out[b][co][pix] ----
    float* ob = out + (size_t)b * COUT * HW;
    #pragma unroll
    for (int mt = 0; mt < 2; mt++) {
        int m = strip * 128 + wm + mt * 16 + (lane >> 2);
        #pragma unroll
        for (int g = 0; g < 4; g++)
            #pragma unroll
            for (int j = 0; j < 2; j++) {
                int co = coBase + wn + g * 16 + j * 8 + (lane & 3) * 2;
                const float* a = acc[mt][g * 2 + j];
                float* p = ob + (size_t)co * HW + m;
                p[0]      = a[0];
                p[HW]     = a[1];
                p[8]      = a[2];
                p[HW + 8] = a[3];
            }
    }
}

// ---------------------------------------------------------------------------
extern "C" void kernel_launch(void* const* d_in, const int* in_sizes, int n_in,
                              void* d_out, int out_size) {
    const float* x       = (const float*)d_in[0];
    const float* w_style = (const float*)d_in[1];
    const float* Wf      = (const float*)d_in[2];
    const float* aff_w   = (const float*)d_in[3];
    const float* aff_b   = (const float*)d_in[4];
    float* out = (float*)d_out;

    style_kernel<<<(B * CIN + 7) / 8, 256>>>(w_style, aff_w, aff_b);
    modulate_kernel<<<dim3(COUT, B), 256>>>(Wf);
    split_kernel<<<dim3(HW / 32, CIN / 32, B), dim3(32, 8)>>>(x);

    cudaFuncSetAttribute(conv_kernel, cudaFuncAttributeMaxDynamicSharedMemorySize, SMEM_TOTAL);
    conv_kernel<<<dim3(32, 2, B), 256, SMEM_TOTAL>>>(out);
}